// round 15
// baseline (speedup 1.0000x reference)
#include <cuda_runtime.h>
#include <cuda_bf16.h>
#include <cstdint>
#include <cstddef>

#define NB 8
#define CC 512
#define WW 8192
#define HH 8

typedef __nv_bfloat16 bf16;

// ---------------- scratch (device globals; allocation-free) ----------------
__device__ bf16  g_xt  [(size_t)NB * WW * CC];   // x transposed [n][w][c] bf16
__device__ bf16  g_wb  [3 * CC * CC];            // Wk,Wq,Wv bf16
__device__ bf16  g_keysb[(size_t)NB * CC * WW];  // keys [n][c][w] bf16
__device__ bf16  g_valsb[(size_t)NB * CC * WW];  // values
__device__ bf16  g_sqt [(size_t)NB * WW * CC];   // softmax(Q) transposed [n][w][c]
__device__ bf16  g_Mb  [(size_t)NB * CC * CC];   // folded Wr@ctx^T (bf16)
__device__ float g_rows[NB * CC];                // sum(exp(keys)) per row
__device__ float g_ctxp[64 * 8 * 64 * 64];       // ctx partials

// ---------------- helpers (arch-neutral: ldmatrix / mma.sync / cp.async) ----
__device__ __forceinline__ uint32_t smem_u32(const void* p) {
    uint32_t a;
    asm("{ .reg .u64 t; cvta.to.shared.u64 t, %1; cvt.u32.u64 %0, t; }"
        : "=r"(a) : "l"(p));
    return a;
}
__device__ __forceinline__ void ldmx4(uint32_t* r, uint32_t addr) {
    asm volatile("ldmatrix.sync.aligned.m8n8.x4.shared.b16 {%0,%1,%2,%3}, [%4];"
                 : "=r"(r[0]), "=r"(r[1]), "=r"(r[2]), "=r"(r[3]) : "r"(addr));
}
__device__ __forceinline__ void mma_bf16(float* c, const uint32_t* a,
                                         const uint32_t b0, const uint32_t b1) {
    asm volatile(
        "mma.sync.aligned.m16n8k16.row.col.f32.bf16.bf16.f32 "
        "{%0,%1,%2,%3}, {%4,%5,%6,%7}, {%8,%9}, {%0,%1,%2,%3};"
        : "+f"(c[0]), "+f"(c[1]), "+f"(c[2]), "+f"(c[3])
        : "r"(a[0]), "r"(a[1]), "r"(a[2]), "r"(a[3]), "r"(b0), "r"(b1));
}
__device__ __forceinline__ void cp16(uint32_t dst, const void* src) {
    asm volatile("cp.async.cg.shared.global [%0], [%1], 16;" :: "r"(dst), "l"(src));
}
__device__ __forceinline__ void cp_commit() {
    asm volatile("cp.async.commit_group;");
}
template <int N>
__device__ __forceinline__ void cp_wait() {
    asm volatile("cp.async.wait_group %0;" :: "n"(N));
}

// ---------------------------------------------------------------------------
// Multi-section HMMA GEMM body with CTA-resident B:
//   for s in 0..nsect: D_s[256 x 128] = A_s[256 x 512] * B[colbase..+128,512]^T
// B tile (16 chunks, 160 KB padded) loaded ONCE; A streamed (3 stages).
// mode per section: 0 = fp32 out + residual; 1 = bf16 out;
//       2 = bf16 + per-head column softmax + transposed write to g_sqt
//       (mode 2 must be the LAST section: its transpose reuses the B region)
// 512 threads, 16 warps, warp tile 64x32, BK=32.
// ---------------------------------------------------------------------------
#define BK 32
#define STRD 40                      // smem row stride (80 B; ldmatrix conflict-free)
#define NA 3                         // A stages
#define A_ELEMS (256 * STRD)         // 10240
#define B_ELEMS (128 * STRD)         // 5120
#define SMEM_ELEMS (NA * A_ELEMS + 16 * B_ELEMS)   // 112640
#define SMEMSZ (SMEM_ELEMS * 2)      // 225280 B
#define TSTR 264                     // transposed Q tile row stride (elements)

__device__ __forceinline__ void issue_A(const bf16* __restrict__ Asec,
                                        bf16* As, int stage, int k0, int tid)
{
    uint32_t sa = smem_u32(As + (size_t)stage * A_ELEMS);
#pragma unroll
    for (int p = 0; p < 2; ++p) {
        int idx = tid + p * 512;
        int row = idx >> 2;                  // 0..255
        int seg = (idx & 3) << 3;            // 0,8,16,24
        cp16(sa + (uint32_t)(row * STRD + seg) * 2,
             Asec + (size_t)row * 512 + k0 + seg);
    }
}

__device__ __forceinline__ void issue_B(const bf16* __restrict__ B,
                                        bf16* Bs, int chunk, int colbase, int tid)
{
    uint32_t sb = smem_u32(Bs + (size_t)chunk * B_ELEMS);
    int rb = tid >> 2;                       // 0..127
    int segb = (tid & 3) << 3;
    cp16(sb + (uint32_t)(rb * STRD + segb) * 2,
         B + (size_t)(colbase + rb) * 512 + chunk * BK + segb);
}

__device__ __forceinline__ void mm_body(
    const bf16* const* Alist,            // nsect A slabs (each 256x512)
    const float* const* biaslist,        // per-section bias (pre-offset, [256])
    void* const* outlist,                // per-section output base (pre-offset)
    const int* modelist,
    const float* __restrict__ resid,     // for mode 0
    const bf16* __restrict__ B,          // [8192 x 512] per-batch slab
    int nsect)
{
    extern __shared__ bf16 dsm[];
    bf16* As = dsm;
    bf16* Bs = dsm + (size_t)NA * A_ELEMS;

    const int tid = threadIdx.x;
    const int lane = tid & 31;
    const int wid = tid >> 5;                // 0..15
    const int wm = (wid & 3) * 64;           // warp M base (0..192)
    const int wn = (wid >> 2) * 32;          // warp N base (0..96)
    const int colbase = blockIdx.x * 128;

    const uint32_t aoff0 =
        (uint32_t)((wm + (lane & 15)) * STRD + ((lane >> 4) << 3));
    const uint32_t boffE[2] = {
        (uint32_t)((wn + (lane & 7) + ((lane >> 4) << 3)) * STRD
                   + (((lane >> 3) & 1) << 3)),
        (uint32_t)((wn + 16 + (lane & 7) + ((lane >> 4) << 3)) * STRD
                   + (((lane >> 3) & 1) << 3)) };

    const int tmax = nsect * 16;

    // prologue: A chunks 0,1 then the whole B tile (one group per chunk)
    issue_A(Alist[0], As, 0, 0, tid);  cp_commit();
    issue_A(Alist[0], As, 1, BK, tid); cp_commit();
#pragma unroll
    for (int c = 0; c < 16; ++c) {
        issue_B(B, Bs, c, colbase, tid);
        cp_commit();
    }
    // committed = 18; in-loop: one commit per iter.
    // A chunk t lives in group {t=0:1, t=1:2, t>=2:17+t}; cp_wait<1> at iter t
    // guarantees groups <= 17+t complete (incl. all B needed by then).

    const int mrow = wm + (lane >> 2);
    const int ncol = wn + 2 * (lane & 3);

    for (int s = 0; s < nsect; ++s) {
        float acc[4][4][4] = {};
        for (int ch = 0; ch < 16; ++ch) {
            const int t = s * 16 + ch;
            cp_wait<1>();
            __syncthreads();
            const uint32_t sa = smem_u32(As + (size_t)(t % NA) * A_ELEMS);
            const uint32_t sb = smem_u32(Bs + (size_t)ch * B_ELEMS);

#pragma unroll
            for (int ks = 0; ks < 2; ++ks) {
                uint32_t a[4][4], b[2][4];
                const uint32_t kk = (uint32_t)(ks * 16) * 2;
#pragma unroll
                for (int i = 0; i < 4; ++i)
                    ldmx4(a[i], sa + (aoff0 + (uint32_t)(i * 16) * STRD) * 2 + kk);
#pragma unroll
                for (int j2 = 0; j2 < 2; ++j2)
                    ldmx4(b[j2], sb + boffE[j2] * 2 + kk);
#pragma unroll
                for (int i = 0; i < 4; ++i)
#pragma unroll
                    for (int j = 0; j < 4; ++j)
                        mma_bf16(acc[i][j], a[i], b[j >> 1][(j & 1) * 2],
                                 b[j >> 1][(j & 1) * 2 + 1]);
            }

            const int tn = t + 2;            // prefetch A chunk t+2
            if (tn < tmax)
                issue_A(Alist[tn >> 4], As, tn % NA, (tn & 15) * BK, tid);
            cp_commit();                     // always commit (group accounting)
        }

        // ---- epilogue for section s ----
        const int mode = modelist[s];
        const float* bias = biaslist[s];
        void* outp = outlist[s];

        if (mode == 2) {
#pragma unroll
            for (int i = 0; i < 4; ++i) {
                float b0 = bias[mrow + i * 16], b1 = bias[mrow + i * 16 + 8];
#pragma unroll
                for (int j = 0; j < 4; ++j) {
                    acc[i][j][0] += b0; acc[i][j][1] += b0;
                    acc[i][j][2] += b1; acc[i][j][3] += b1;
                }
            }
            // per-column softmax over this warp's 64 rows (one head)
#pragma unroll
            for (int j = 0; j < 4; ++j)
#pragma unroll
                for (int q = 0; q < 2; ++q) {
                    float mx = -1e30f;
#pragma unroll
                    for (int i = 0; i < 4; ++i)
                        mx = fmaxf(mx, fmaxf(acc[i][j][q], acc[i][j][q + 2]));
                    mx = fmaxf(mx, __shfl_xor_sync(0xffffffffu, mx, 4));
                    mx = fmaxf(mx, __shfl_xor_sync(0xffffffffu, mx, 8));
                    mx = fmaxf(mx, __shfl_xor_sync(0xffffffffu, mx, 16));
                    float ssum = 0.f;
#pragma unroll
                    for (int i = 0; i < 4; ++i) {
                        acc[i][j][q]     = __expf(acc[i][j][q] - mx);
                        acc[i][j][q + 2] = __expf(acc[i][j][q + 2] - mx);
                        ssum += acc[i][j][q] + acc[i][j][q + 2];
                    }
                    ssum += __shfl_xor_sync(0xffffffffu, ssum, 4);
                    ssum += __shfl_xor_sync(0xffffffffu, ssum, 8);
                    ssum += __shfl_xor_sync(0xffffffffu, ssum, 16);
                    float inv = 1.f / ssum;
#pragma unroll
                    for (int i = 0; i < 4; ++i) {
                        acc[i][j][q] *= inv; acc[i][j][q + 2] *= inv;
                    }
                }
            // transpose through the (now dead) B region
            __syncthreads();
            bf16* tile = Bs;                 // [128 w][TSTR channels]
#pragma unroll
            for (int i = 0; i < 4; ++i) {
                int m0 = mrow + i * 16;
#pragma unroll
                for (int j = 0; j < 4; ++j) {
                    int nb = ncol + j * 8;
                    float* c = acc[i][j];
                    tile[(size_t)nb * TSTR + m0]           = __float2bfloat16(c[0]);
                    tile[(size_t)(nb + 1) * TSTR + m0]     = __float2bfloat16(c[1]);
                    tile[(size_t)nb * TSTR + m0 + 8]       = __float2bfloat16(c[2]);
                    tile[(size_t)(nb + 1) * TSTR + m0 + 8] = __float2bfloat16(c[3]);
                }
            }
            __syncthreads();
            bf16* oq = (bf16*)outp;
#pragma unroll
            for (int p = 0; p < 8; ++p) {
                int idx = tid + p * 512;
                int nl = idx >> 5;               // w row 0..127
                int seg = (idx & 31) * 8;        // channel 0..248
                *(uint4*)(oq + (size_t)(colbase + nl) * CC + seg) =
                    *(uint4*)&tile[(size_t)nl * TSTR + seg];
            }
        } else {
            const int ncolg = colbase + ncol;
#pragma unroll
            for (int i = 0; i < 4; ++i) {
                int m0 = mrow + i * 16;
                float b0 = bias[m0];
                float b1 = bias[m0 + 8];
#pragma unroll
                for (int j = 0; j < 4; ++j) {
                    int n = ncolg + j * 8;
                    float* c = acc[i][j];
                    if (mode == 1) {
                        bf16* o = (bf16*)outp;
                        *(__nv_bfloat162*)(o + (size_t)m0 * WW + n) =
                            __floats2bfloat162_rn(c[0] + b0, c[1] + b0);
                        *(__nv_bfloat162*)(o + (size_t)(m0 + 8) * WW + n) =
                            __floats2bfloat162_rn(c[2] + b1, c[3] + b1);
                    } else {
                        float* o = (float*)outp;
                        float2 r0v = *(const float2*)(resid + (size_t)m0 * WW + n);
                        float2 r1v = *(const float2*)(resid + (size_t)(m0 + 8) * WW + n);
                        float2 o0 = { c[0] + b0 + r0v.x, c[1] + b0 + r0v.y };
                        float2 o1 = { c[2] + b1 + r1v.x, c[3] + b1 + r1v.y };
                        *(float2*)(o + (size_t)m0 * WW + n) = o0;
                        *(float2*)(o + (size_t)(m0 + 8) * WW + n) = o1;
                    }
                }
            }
        }
    }
}

// ---------------------------------------------------------------------------
// single conversion kernel: all 3 weights + zero g_rows
// ---------------------------------------------------------------------------
__global__ void __launch_bounds__(256)
k_convw_all(const float* __restrict__ Wk, const float* __restrict__ Wq,
            const float* __restrict__ Wv, bf16* __restrict__ d)
{
    int gid = blockIdx.x * 256 + threadIdx.x;          // 0..196607
    if (gid < NB * CC) g_rows[gid] = 0.f;
    int sect = gid >> 16;
    int local = gid & 65535;
    const float* s = (sect == 0 ? Wk : sect == 1 ? Wq : Wv);
    int i = local * 4;
    float4 v = *(const float4*)(s + i);
    __nv_bfloat162 o[2];
    o[0] = __floats2bfloat162_rn(v.x, v.y);
    o[1] = __floats2bfloat162_rn(v.z, v.w);
    *(uint2*)(d + (size_t)sect * 262144 + i) = *(uint2*)o;
}

// 64x64 transpose tiles: 128B-coalesced reads and (bf16x2-packed) writes
__global__ void __launch_bounds__(256)
k_convx(const float* __restrict__ x)
{
    __shared__ float tile[64][65];
    int n = blockIdx.z, c0 = blockIdx.y * 64, w0 = blockIdx.x * 64;
    int t = threadIdx.x;
    int tx = t & 63, ty = t >> 6;
    const float* xb = x + (size_t)n * CC * WW;
#pragma unroll
    for (int i = ty; i < 64; i += 4)
        tile[i][tx] = xb[(size_t)(c0 + i) * WW + w0 + tx];
    __syncthreads();
    bf16* ob = g_xt + (size_t)n * WW * CC;
    int cpair = (t & 31) * 2, wr = t >> 5;
#pragma unroll
    for (int i = wr; i < 64; i += 8) {
        __nv_bfloat162 v = __floats2bfloat162_rn(tile[cpair][i], tile[cpair + 1][i]);
        *(__nv_bfloat162*)(ob + (size_t)(w0 + i) * CC + c0 + cpair) = v;
    }
}

// ---------------------------------------------------------------------------
// GEMM wrappers
// ---------------------------------------------------------------------------
__global__ void __launch_bounds__(512, 1)
k_proj(const float* __restrict__ bk, const float* __restrict__ bq,
       const float* __restrict__ bv)
{
    int mbrow = blockIdx.y * 256;            // m-half
    int n = blockIdx.z;
    // section order K, V, Q (Q last: mode-2 epilogue reuses B region)
    const bf16* Alist[3] = {
        g_wb + (size_t)0 * 262144 + (size_t)mbrow * CC,   // Wk
        g_wb + (size_t)2 * 262144 + (size_t)mbrow * CC,   // Wv
        g_wb + (size_t)1 * 262144 + (size_t)mbrow * CC }; // Wq
    const float* biaslist[3] = { bk + mbrow, bv + mbrow, bq + mbrow };
    void* outlist[3] = {
        g_keysb + (size_t)n * CC * WW + (size_t)mbrow * WW,
        g_valsb + (size_t)n * CC * WW + (size_t)mbrow * WW,
        g_sqt + (size_t)n * WW * CC + mbrow };
    const int modelist[3] = { 1, 1, 2 };
    const bf16* B = g_xt + (size_t)n * WW * CC;
    mm_body(Alist, biaslist, outlist, modelist, nullptr, B, 3);
}

__global__ void __launch_bounds__(512, 1)
k_out(const float* __restrict__ x, const float* __restrict__ br,
      float* __restrict__ out)
{
    int mbrow = blockIdx.y * 256;
    int n = blockIdx.z;
    const bf16* Alist[1] = { g_Mb + (size_t)n * CC * CC + (size_t)mbrow * CC };
    const float* biaslist[1] = { br + mbrow };
    void* outlist[1] = { out + (size_t)n * CC * WW + (size_t)mbrow * WW };
    const int modelist[1] = { 0 };
    const float* resid = x + (size_t)n * CC * WW + (size_t)mbrow * WW;
    const bf16* B = g_sqt + (size_t)n * WW * CC;
    mm_body(Alist, biaslist, outlist, modelist, resid, B, 1);
}

// ---------------------------------------------------------------------------
// ctx partials via HMMA: exp(K) @ V^T over 1024-wide w chunks, fused row sums.
// grid (64 nh, 8 chunks), 256 threads. smem [64][72] bf16, double-buffered.
// ---------------------------------------------------------------------------
#define CSTRD 72

__global__ void __launch_bounds__(256) k_ctx()
{
    __shared__ bf16 Ks[2][64 * CSTRD];
    __shared__ bf16 Vs[2][64 * CSTRD];

    int nh = blockIdx.x, chunk = blockIdx.y, t = threadIdx.x;
    int lane = t & 31, wid = t >> 5;
    int rowbase = nh * 64;
    int wbase = chunk * 1024;
    int lr = t >> 2;
    int seg = (t & 3) * 16;
    const bf16* kg = g_keysb + (size_t)(rowbase + lr) * WW + wbase + seg;
    const bf16* vg = g_valsb + (size_t)(rowbase + lr) * WW + wbase + seg;

    int wm = (wid & 3) * 16;
    int wn = (wid >> 2) * 32;

    float acc[4][4] = {};
    float srow = 0.f;

    uint4 kr[2], vr[2];
    kr[0] = *(const uint4*)kg;       kr[1] = *(const uint4*)(kg + 8);
    vr[0] = *(const uint4*)vg;       vr[1] = *(const uint4*)(vg + 8);

    for (int s = 0; s < 16; ++s) {
        const int b = s & 1;
        uint4 ke[2];
#pragma unroll
        for (int u = 0; u < 2; ++u) {
            const __nv_bfloat162* kh = (const __nv_bfloat162*)&kr[u];
            __nv_bfloat162* eo = (__nv_bfloat162*)&ke[u];
#pragma unroll
            for (int i = 0; i < 4; ++i) {
                float2 f = __bfloat1622float2(kh[i]);
                float e0 = __expf(f.x), e1 = __expf(f.y);
                srow += e0 + e1;
                eo[i] = __floats2bfloat162_rn(e0, e1);
            }
        }
        bf16* kst = &Ks[b][lr * CSTRD + seg];
        bf16* vst = &Vs[b][lr * CSTRD + seg];
        *(uint4*)kst = ke[0];        *(uint4*)(kst + 8) = ke[1];
        *(uint4*)vst = vr[0];        *(uint4*)(vst + 8) = vr[1];
        __syncthreads();
        if (s < 15) {
            const bf16* kg2 = kg + (s + 1) * 64;
            const bf16* vg2 = vg + (s + 1) * 64;
            kr[0] = *(const uint4*)kg2; kr[1] = *(const uint4*)(kg2 + 8);
            vr[0] = *(const uint4*)vg2; vr[1] = *(const uint4*)(vg2 + 8);
        }
        const uint32_t sk = smem_u32(&Ks[b][0]);
        const uint32_t sv = smem_u32(&Vs[b][0]);
#pragma unroll
        for (int ks = 0; ks < 4; ++ks) {
            uint32_t a[4], bb[2][4];
            const int kA = ks * 16 + ((lane >> 4) << 3);
            const int kB = ks * 16 + (((lane >> 3) & 1) << 3);
            ldmx4(a, sk + (uint32_t)((wm + (lane & 15)) * CSTRD + kA) * 2);
#pragma unroll
            for (int j2 = 0; j2 < 2; ++j2)
                ldmx4(bb[j2], sv +
                      (uint32_t)((wn + j2 * 16 + (lane & 7) + ((lane >> 4) << 3))
                                 * CSTRD + kB) * 2);
#pragma unroll
            for (int j = 0; j < 4; ++j)
                mma_bf16(acc[j], a, bb[j >> 1][(j & 1) * 2],
                         bb[j >> 1][(j & 1) * 2 + 1]);
        }
    }

    srow += __shfl_xor_sync(0xffffffffu, srow, 1);
    srow += __shfl_xor_sync(0xffffffffu, srow, 2);
    if ((t & 3) == 0) atomicAdd(&g_rows[rowbase + lr], srow);

    float* op = g_ctxp + (size_t)(nh * 8 + chunk) * 4096;
    int r0 = wm + (lane >> 2);
    int c0 = wn + (lane & 3) * 2;
#pragma unroll
    for (int j = 0; j < 4; ++j) {
        int c = c0 + j * 8;
        op[r0 * 64 + c]           = acc[j][0];
        op[r0 * 64 + c + 1]       = acc[j][1];
        op[(r0 + 8) * 64 + c]     = acc[j][2];
        op[(r0 + 8) * 64 + c + 1] = acc[j][3];
    }
}

// ---------------------------------------------------------------------------
// M[n][c][h*64+k] = sum_v Wr[c][h*64+v] * ctx[n][h][k][v]  (bf16 out)
// ctx partial reduction + 1/rowsum fused here (ctxp is L2-resident).
// ---------------------------------------------------------------------------
__global__ void __launch_bounds__(256) k_M(const float* __restrict__ Wr)
{
    int ct = blockIdx.x, h = blockIdx.y, n = blockIdx.z;
    __shared__ float Ws[64][65];
    __shared__ float Cs[64][65];
    int t = threadIdx.x;
    int nh = n * 8 + h;

    for (int e = t; e < 4096; e += 256) {
        int r = e >> 6, c = e & 63;
        Ws[r][c] = Wr[(size_t)(ct * 64 + r) * 512 + h * 64 + c];
        float sum = 0.f;
#pragma unroll
        for (int ch = 0; ch < 8; ++ch)
            sum += g_ctxp[(size_t)(nh * 8 + ch) * 4096 + e];
        Cs[r][c] = sum / g_rows[nh * 64 + r];
    }
    __syncthreads();

    int c0 = (t >> 4) << 2;
    int k0 = (t & 15) << 2;
    float acc[4][4] = {};
    for (int v = 0; v < 64; ++v) {
        float a_[4], b_[4];
#pragma unroll
        for (int i = 0; i < 4; ++i) a_[i] = Ws[c0 + i][v];
#pragma unroll
        for (int j = 0; j < 4; ++j) b_[j] = Cs[k0 + j][v];
#pragma unroll
        for (int i = 0; i < 4; ++i)
#pragma unroll
            for (int j = 0; j < 4; ++j)
                acc[i][j] = fmaf(a_[i], b_[j], acc[i][j]);
    }
#pragma unroll
    for (int i = 0; i < 4; ++i)
#pragma unroll
        for (int j = 0; j < 4; ++j)
            g_Mb[(size_t)n * 262144 + (size_t)(ct * 64 + c0 + i) * 512 + h * 64 + k0 + j]
                = __float2bfloat16(acc[i][j]);
}

// ---------------------------------------------------------------------------
extern "C" void kernel_launch(void* const* d_in, const int* in_sizes, int n_in,
                              void* d_out, int out_size)
{
    const float* x  = (const float*)d_in[0];
    const float* Wk = (const float*)d_in[1];
    const float* bk = (const float*)d_in[2];
    const float* Wq = (const float*)d_in[3];
    const float* bq = (const float*)d_in[4];
    const float* Wv = (const float*)d_in[5];
    const float* bv = (const float*)d_in[6];
    const float* Wr = (const float*)d_in[7];
    const float* br = (const float*)d_in[8];
    float* out = (float*)d_out;

    bf16* wb;
    cudaGetSymbolAddress((void**)&wb, g_wb);

    cudaFuncSetAttribute(k_proj, cudaFuncAttributeMaxDynamicSharedMemorySize, SMEMSZ);
    cudaFuncSetAttribute(k_out,  cudaFuncAttributeMaxDynamicSharedMemorySize, SMEMSZ);

    k_convw_all<<<768, 256>>>(Wk, Wq, Wv, wb);
    k_convx<<<dim3(128, 8, 8), 256>>>(x);
    k_proj<<<dim3(64, 2, 8), 512, SMEMSZ>>>(bk, bq, bv);
    k_ctx<<<dim3(64, 8), 256>>>();
    k_M<<<dim3(8, 8, 8), 256>>>(Wr);
    k_out<<<dim3(64, 2, 8), 512, SMEMSZ>>>(x, br, out);
}

// round 16
// speedup vs baseline: 1.1255x; 1.1255x over previous
#include <cuda_runtime.h>
#include <cuda_bf16.h>
#include <cstdint>
#include <cstddef>

#define NB 8
#define CC 512
#define WW 8192
#define HH 8

typedef __nv_bfloat16 bf16;

// ---------------- scratch (device globals; allocation-free) ----------------
__device__ bf16  g_xt  [(size_t)NB * WW * CC];   // x transposed [n][w][c] bf16
__device__ bf16  g_wb  [3 * CC * CC];            // Wk,Wq,Wv bf16
__device__ bf16  g_keysb[(size_t)NB * CC * WW];  // keys [n][c][w] bf16
__device__ bf16  g_valsb[(size_t)NB * CC * WW];  // values
__device__ bf16  g_sqt [(size_t)NB * WW * CC];   // softmax(Q) transposed [n][w][c]
__device__ bf16  g_Mb  [(size_t)NB * CC * CC];   // folded Wr@ctx^T (bf16)
__device__ float g_rows[NB * CC];                // sum(exp(keys)) per row
__device__ float g_ctxp[64 * 8 * 64 * 64];       // ctx partials

// ---------------- helpers (arch-neutral: ldmatrix / mma.sync / cp.async) ----
__device__ __forceinline__ uint32_t smem_u32(const void* p) {
    uint32_t a;
    asm("{ .reg .u64 t; cvta.to.shared.u64 t, %1; cvt.u32.u64 %0, t; }"
        : "=r"(a) : "l"(p));
    return a;
}
__device__ __forceinline__ void ldmx4(uint32_t* r, uint32_t addr) {
    asm volatile("ldmatrix.sync.aligned.m8n8.x4.shared.b16 {%0,%1,%2,%3}, [%4];"
                 : "=r"(r[0]), "=r"(r[1]), "=r"(r[2]), "=r"(r[3]) : "r"(addr));
}
__device__ __forceinline__ void mma_bf16(float* c, const uint32_t* a,
                                         const uint32_t b0, const uint32_t b1) {
    asm volatile(
        "mma.sync.aligned.m16n8k16.row.col.f32.bf16.bf16.f32 "
        "{%0,%1,%2,%3}, {%4,%5,%6,%7}, {%8,%9}, {%0,%1,%2,%3};"
        : "+f"(c[0]), "+f"(c[1]), "+f"(c[2]), "+f"(c[3])
        : "r"(a[0]), "r"(a[1]), "r"(a[2]), "r"(a[3]), "r"(b0), "r"(b1));
}
__device__ __forceinline__ void cp16(uint32_t dst, const void* src) {
    asm volatile("cp.async.cg.shared.global [%0], [%1], 16;" :: "r"(dst), "l"(src));
}
__device__ __forceinline__ void cp_commit() {
    asm volatile("cp.async.commit_group;");
}
template <int N>
__device__ __forceinline__ void cp_wait() {
    asm volatile("cp.async.wait_group %0;" :: "n"(N));
}

// ---------------------------------------------------------------------------
// HMMA GEMM body: D[256 x 128] = A[256 x 512] * B[colbase..+128, 512]^T
// bf16 K-major row-major operands. 512 threads, 16 warps (warp tile 64x32),
// 5-stage cp.async pipeline, BK=32.
// mode: 0 = fp32 out + residual; 1 = bf16 out (smem-staged coalesced stores);
//       2 = bf16 + per-head column softmax + transposed write to g_sqt
// ---------------------------------------------------------------------------
#define BK 32
#define STRD 40                      // smem row stride (80 B; ldmatrix conflict-free)
#define NSTAGE 5
#define A_ELEMS (256 * STRD)
#define B_ELEMS (128 * STRD)
#define SMEMSZ (NSTAGE * (A_ELEMS + B_ELEMS) * 2)   // 153600 B
#define TSTR 264                     // transposed Q tile row stride (elements)
#define OSTR 136                     // mode-1 staging row stride (elements)

__device__ __forceinline__ void mm_issue(
    const bf16* __restrict__ A, const bf16* __restrict__ B,
    bf16* As, bf16* Bs, int stage, int k0, int colbase, int tid)
{
    uint32_t sa = smem_u32(As + (size_t)stage * A_ELEMS);
    uint32_t sb = smem_u32(Bs + (size_t)stage * B_ELEMS);
#pragma unroll
    for (int p = 0; p < 2; ++p) {
        int idx = tid + p * 512;
        int row = idx >> 2;                  // 0..255
        int seg = (idx & 3) << 3;            // 0,8,16,24
        cp16(sa + (uint32_t)(row * STRD + seg) * 2,
             A + (size_t)row * 512 + k0 + seg);
    }
    int rb = tid >> 2;                       // 0..127
    int segb = (tid & 3) << 3;
    cp16(sb + (uint32_t)(rb * STRD + segb) * 2,
         B + (size_t)(colbase + rb) * 512 + k0 + segb);
}

__device__ __forceinline__ void mm_body(
    const bf16* __restrict__ A,          // pre-offset to its 256-row slab
    const bf16* __restrict__ B,          // [8192 x 512] per-batch slab
    const float* __restrict__ bias,      // pre-offset [256]
    const float* __restrict__ resid,     // pre-offset rows (or nullptr)
    void* __restrict__ outp,             // pre-offset (mode2: g_sqt + n slab + mbrow)
    int mode)
{
    extern __shared__ bf16 dsm[];
    bf16* As = dsm;
    bf16* Bs = dsm + (size_t)NSTAGE * A_ELEMS;

    const int tid = threadIdx.x;
    const int lane = tid & 31;
    const int wid = tid >> 5;                // 0..15
    const int wm = (wid & 3) * 64;           // warp M base (0..192)
    const int wn = (wid >> 2) * 32;          // warp N base (0..96)
    const int colbase = blockIdx.x * 128;

    // hoisted per-warp ldmatrix offsets (element units, within a stage)
    const uint32_t aoff0 =
        (uint32_t)((wm + (lane & 15)) * STRD + ((lane >> 4) << 3));
    const uint32_t boffE[2] = {
        (uint32_t)((wn + (lane & 7) + ((lane >> 4) << 3)) * STRD
                   + (((lane >> 3) & 1) << 3)),
        (uint32_t)((wn + 16 + (lane & 7) + ((lane >> 4) << 3)) * STRD
                   + (((lane >> 3) & 1) << 3)) };

    float acc[4][4][4] = {};

    // prologue: stages 0..3
#pragma unroll
    for (int s = 0; s < 4; ++s) {
        mm_issue(A, B, As, Bs, s, s * BK, colbase, tid);
        cp_commit();
    }

    for (int ch = 0; ch < 16; ++ch) {
        cp_wait<3>();
        __syncthreads();
        const int cur = ch % NSTAGE;
        const uint32_t sa = smem_u32(As + (size_t)cur * A_ELEMS);
        const uint32_t sb = smem_u32(Bs + (size_t)cur * B_ELEMS);

#pragma unroll
        for (int ks = 0; ks < 2; ++ks) {
            uint32_t a[4][4], b[2][4];
            const uint32_t kk = (uint32_t)(ks * 16) * 2;
#pragma unroll
            for (int i = 0; i < 4; ++i)
                ldmx4(a[i], sa + (aoff0 + (uint32_t)(i * 16) * STRD) * 2 + kk);
#pragma unroll
            for (int j2 = 0; j2 < 2; ++j2)
                ldmx4(b[j2], sb + boffE[j2] * 2 + kk);
#pragma unroll
            for (int i = 0; i < 4; ++i)
#pragma unroll
                for (int j = 0; j < 4; ++j)
                    mma_bf16(acc[i][j], a[i], b[j >> 1][(j & 1) * 2],
                             b[j >> 1][(j & 1) * 2 + 1]);
        }

        if (ch + 4 < 16)
            mm_issue(A, B, As, Bs, (ch + 4) % NSTAGE, (ch + 4) * BK,
                     colbase, tid);
        cp_commit();  // always commit (possibly empty) to keep group accounting
    }

    const int mrow = wm + (lane >> 2);
    const int ncol = wn + 2 * (lane & 3);

    if (mode == 2) {
        // bias in place
#pragma unroll
        for (int i = 0; i < 4; ++i) {
            float b0 = bias[mrow + i * 16], b1 = bias[mrow + i * 16 + 8];
#pragma unroll
            for (int j = 0; j < 4; ++j) {
                acc[i][j][0] += b0; acc[i][j][1] += b0;
                acc[i][j][2] += b1; acc[i][j][3] += b1;
            }
        }
        // per-column softmax over this warp's 64 rows (exactly one head)
#pragma unroll
        for (int j = 0; j < 4; ++j)
#pragma unroll
            for (int q = 0; q < 2; ++q) {
                float mx = -1e30f;
#pragma unroll
                for (int i = 0; i < 4; ++i)
                    mx = fmaxf(mx, fmaxf(acc[i][j][q], acc[i][j][q + 2]));
                mx = fmaxf(mx, __shfl_xor_sync(0xffffffffu, mx, 4));
                mx = fmaxf(mx, __shfl_xor_sync(0xffffffffu, mx, 8));
                mx = fmaxf(mx, __shfl_xor_sync(0xffffffffu, mx, 16));
                float s = 0.f;
#pragma unroll
                for (int i = 0; i < 4; ++i) {
                    acc[i][j][q]     = __expf(acc[i][j][q] - mx);
                    acc[i][j][q + 2] = __expf(acc[i][j][q + 2] - mx);
                    s += acc[i][j][q] + acc[i][j][q + 2];
                }
                s += __shfl_xor_sync(0xffffffffu, s, 4);
                s += __shfl_xor_sync(0xffffffffu, s, 8);
                s += __shfl_xor_sync(0xffffffffu, s, 16);
                float inv = 1.f / s;
#pragma unroll
                for (int i = 0; i < 4; ++i) {
                    acc[i][j][q] *= inv; acc[i][j][q + 2] *= inv;
                }
            }
        // transpose through smem (pipeline buffers are dead now)
        __syncthreads();
        bf16* tile = dsm;                    // [128 w][TSTR] channels
#pragma unroll
        for (int i = 0; i < 4; ++i) {
            int m0 = mrow + i * 16;
#pragma unroll
            for (int j = 0; j < 4; ++j) {
                int nb = ncol + j * 8;
                float* c = acc[i][j];
                tile[(size_t)nb * TSTR + m0]           = __float2bfloat16(c[0]);
                tile[(size_t)(nb + 1) * TSTR + m0]     = __float2bfloat16(c[1]);
                tile[(size_t)nb * TSTR + m0 + 8]       = __float2bfloat16(c[2]);
                tile[(size_t)(nb + 1) * TSTR + m0 + 8] = __float2bfloat16(c[3]);
            }
        }
        __syncthreads();
        // coalesced store: g_sqt[(colbase+w)*CC + mbrow + c]
        bf16* oq = (bf16*)outp;
#pragma unroll
        for (int p = 0; p < 8; ++p) {
            int idx = tid + p * 512;
            int nl = idx >> 5;               // 0..127
            int seg = (idx & 31) * 8;        // 0..248
            *(uint4*)(oq + (size_t)(colbase + nl) * CC + seg) =
                *(uint4*)&tile[(size_t)nl * TSTR + seg];
        }
        return;
    }

    if (mode == 1) {
        // stage bf16 tile in (dead) pipeline smem for full-sector stores
        __syncthreads();
        bf16* tile = dsm;                    // [256 m][OSTR cols]
#pragma unroll
        for (int i = 0; i < 4; ++i) {
            int m0 = mrow + i * 16;
            float b0 = bias[m0];
            float b1 = bias[m0 + 8];
#pragma unroll
            for (int j = 0; j < 4; ++j) {
                int nb = ncol + j * 8;       // local col 0..127
                float* c = acc[i][j];
                *(__nv_bfloat162*)&tile[(size_t)m0 * OSTR + nb] =
                    __floats2bfloat162_rn(c[0] + b0, c[1] + b0);
                *(__nv_bfloat162*)&tile[(size_t)(m0 + 8) * OSTR + nb] =
                    __floats2bfloat162_rn(c[2] + b1, c[3] + b1);
            }
        }
        __syncthreads();
        bf16* o = (bf16*)outp;
#pragma unroll
        for (int p = 0; p < 8; ++p) {
            int idx = tid + p * 512;
            int row = idx >> 4;              // 0..255
            int seg = (idx & 15) * 8;        // 0..120
            *(uint4*)(o + (size_t)row * WW + colbase + seg) =
                *(uint4*)&tile[(size_t)row * OSTR + seg];
        }
        return;
    }

    // mode 0: fp32 + residual (stores are already full-sector)
    const int ncolg = colbase + ncol;
#pragma unroll
    for (int i = 0; i < 4; ++i) {
        int m0 = mrow + i * 16;
        float b0 = bias[m0];
        float b1 = bias[m0 + 8];
#pragma unroll
        for (int j = 0; j < 4; ++j) {
            int n = ncolg + j * 8;
            float* c = acc[i][j];
            float* o = (float*)outp;
            float2 r0v = *(const float2*)(resid + (size_t)m0 * WW + n);
            float2 r1v = *(const float2*)(resid + (size_t)(m0 + 8) * WW + n);
            float2 o0 = { c[0] + b0 + r0v.x, c[1] + b0 + r0v.y };
            float2 o1 = { c[2] + b1 + r1v.x, c[3] + b1 + r1v.y };
            *(float2*)(o + (size_t)m0 * WW + n) = o0;
            *(float2*)(o + (size_t)(m0 + 8) * WW + n) = o1;
        }
    }
}

// ---------------------------------------------------------------------------
// single conversion kernel: all 3 weights + zero g_rows
// ---------------------------------------------------------------------------
__global__ void __launch_bounds__(256)
k_convw_all(const float* __restrict__ Wk, const float* __restrict__ Wq,
            const float* __restrict__ Wv, bf16* __restrict__ d)
{
    int gid = blockIdx.x * 256 + threadIdx.x;          // 0..196607
    if (gid < NB * CC) g_rows[gid] = 0.f;
    int sect = gid >> 16;
    int local = gid & 65535;
    const float* s = (sect == 0 ? Wk : sect == 1 ? Wq : Wv);
    int i = local * 4;
    float4 v = *(const float4*)(s + i);
    __nv_bfloat162 o[2];
    o[0] = __floats2bfloat162_rn(v.x, v.y);
    o[1] = __floats2bfloat162_rn(v.z, v.w);
    *(uint2*)(d + (size_t)sect * 262144 + i) = *(uint2*)o;
}

// 64x64 transpose tiles: 128B-coalesced reads and (bf16x2-packed) writes
__global__ void __launch_bounds__(256)
k_convx(const float* __restrict__ x)
{
    __shared__ float tile[64][65];
    int n = blockIdx.z, c0 = blockIdx.y * 64, w0 = blockIdx.x * 64;
    int t = threadIdx.x;
    int tx = t & 63, ty = t >> 6;
    const float* xb = x + (size_t)n * CC * WW;
#pragma unroll
    for (int i = ty; i < 64; i += 4)
        tile[i][tx] = xb[(size_t)(c0 + i) * WW + w0 + tx];
    __syncthreads();
    bf16* ob = g_xt + (size_t)n * WW * CC;
    int cpair = (t & 31) * 2, wr = t >> 5;
#pragma unroll
    for (int i = wr; i < 64; i += 8) {
        __nv_bfloat162 v = __floats2bfloat162_rn(tile[cpair][i], tile[cpair + 1][i]);
        *(__nv_bfloat162*)(ob + (size_t)(w0 + i) * CC + c0 + cpair) = v;
    }
}

// ---------------------------------------------------------------------------
// GEMM wrappers
// ---------------------------------------------------------------------------
__global__ void __launch_bounds__(512, 1)
k_proj(const float* __restrict__ bk, const float* __restrict__ bq,
       const float* __restrict__ bv)
{
    int mtile = blockIdx.y;                  // 0..5
    int sect = mtile >> 1;                   // 0=K 1=Q 2=V
    int mbrow = (mtile & 1) * 256;
    int n = blockIdx.z;
    const bf16* A = g_wb + (size_t)sect * CC * CC + (size_t)mbrow * CC;
    const bf16* B = g_xt + (size_t)n * WW * CC;
    const float* bias = (sect == 0 ? bk : sect == 1 ? bq : bv) + mbrow;
    if (sect == 1) {
        bf16* out = g_sqt + (size_t)n * WW * CC + mbrow;   // channel offset
        mm_body(A, B, bias, nullptr, out, 2);
    } else {
        bf16* out = (sect == 0 ? g_keysb : g_valsb)
                    + (size_t)n * CC * WW + (size_t)mbrow * WW;
        mm_body(A, B, bias, nullptr, out, 1);
    }
}

__global__ void __launch_bounds__(512, 1)
k_out(const float* __restrict__ x, const float* __restrict__ br,
      float* __restrict__ out)
{
    int mbrow = blockIdx.y * 256;
    int n = blockIdx.z;
    const bf16* A = g_Mb + (size_t)n * CC * CC + (size_t)mbrow * CC;
    const bf16* B = g_sqt + (size_t)n * WW * CC;
    const float* resid = x + (size_t)n * CC * WW + (size_t)mbrow * WW;
    float* O = out + (size_t)n * CC * WW + (size_t)mbrow * WW;
    mm_body(A, B, br + mbrow, resid, O, 0);
}

// ---------------------------------------------------------------------------
// ctx partials via HMMA: exp(K) @ V^T over 1024-wide w chunks, fused row sums.
// grid (64 nh, 8 chunks), 256 threads. smem [64][72] bf16, double-buffered.
// ---------------------------------------------------------------------------
#define CSTRD 72

__global__ void __launch_bounds__(256) k_ctx()
{
    __shared__ bf16 Ks[2][64 * CSTRD];
    __shared__ bf16 Vs[2][64 * CSTRD];

    int nh = blockIdx.x, chunk = blockIdx.y, t = threadIdx.x;
    int lane = t & 31, wid = t >> 5;
    int rowbase = nh * 64;
    int wbase = chunk * 1024;
    int lr = t >> 2;
    int seg = (t & 3) * 16;
    const bf16* kg = g_keysb + (size_t)(rowbase + lr) * WW + wbase + seg;
    const bf16* vg = g_valsb + (size_t)(rowbase + lr) * WW + wbase + seg;

    int wm = (wid & 3) * 16;
    int wn = (wid >> 2) * 32;

    float acc[4][4] = {};
    float srow = 0.f;

    uint4 kr[2], vr[2];
    kr[0] = *(const uint4*)kg;       kr[1] = *(const uint4*)(kg + 8);
    vr[0] = *(const uint4*)vg;       vr[1] = *(const uint4*)(vg + 8);

    for (int s = 0; s < 16; ++s) {
        const int b = s & 1;
        uint4 ke[2];
#pragma unroll
        for (int u = 0; u < 2; ++u) {
            const __nv_bfloat162* kh = (const __nv_bfloat162*)&kr[u];
            __nv_bfloat162* eo = (__nv_bfloat162*)&ke[u];
#pragma unroll
            for (int i = 0; i < 4; ++i) {
                float2 f = __bfloat1622float2(kh[i]);
                float e0 = __expf(f.x), e1 = __expf(f.y);
                srow += e0 + e1;
                eo[i] = __floats2bfloat162_rn(e0, e1);
            }
        }
        bf16* kst = &Ks[b][lr * CSTRD + seg];
        bf16* vst = &Vs[b][lr * CSTRD + seg];
        *(uint4*)kst = ke[0];        *(uint4*)(kst + 8) = ke[1];
        *(uint4*)vst = vr[0];        *(uint4*)(vst + 8) = vr[1];
        __syncthreads();
        if (s < 15) {
            const bf16* kg2 = kg + (s + 1) * 64;
            const bf16* vg2 = vg + (s + 1) * 64;
            kr[0] = *(const uint4*)kg2; kr[1] = *(const uint4*)(kg2 + 8);
            vr[0] = *(const uint4*)vg2; vr[1] = *(const uint4*)(vg2 + 8);
        }
        const uint32_t sk = smem_u32(&Ks[b][0]);
        const uint32_t sv = smem_u32(&Vs[b][0]);
#pragma unroll
        for (int ks = 0; ks < 4; ++ks) {
            uint32_t a[4], bb[2][4];
            const int kA = ks * 16 + ((lane >> 4) << 3);
            const int kB = ks * 16 + (((lane >> 3) & 1) << 3);
            ldmx4(a, sk + (uint32_t)((wm + (lane & 15)) * CSTRD + kA) * 2);
#pragma unroll
            for (int j2 = 0; j2 < 2; ++j2)
                ldmx4(bb[j2], sv +
                      (uint32_t)((wn + j2 * 16 + (lane & 7) + ((lane >> 4) << 3))
                                 * CSTRD + kB) * 2);
#pragma unroll
            for (int j = 0; j < 4; ++j)
                mma_bf16(acc[j], a, bb[j >> 1][(j & 1) * 2],
                         bb[j >> 1][(j & 1) * 2 + 1]);
        }
    }

    srow += __shfl_xor_sync(0xffffffffu, srow, 1);
    srow += __shfl_xor_sync(0xffffffffu, srow, 2);
    if ((t & 3) == 0) atomicAdd(&g_rows[rowbase + lr], srow);

    float* op = g_ctxp + (size_t)(nh * 8 + chunk) * 4096;
    int r0 = wm + (lane >> 2);
    int c0 = wn + (lane & 3) * 2;
#pragma unroll
    for (int j = 0; j < 4; ++j) {
        int c = c0 + j * 8;
        op[r0 * 64 + c]           = acc[j][0];
        op[r0 * 64 + c + 1]       = acc[j][1];
        op[(r0 + 8) * 64 + c]     = acc[j][2];
        op[(r0 + 8) * 64 + c + 1] = acc[j][3];
    }
}

// ---------------------------------------------------------------------------
// M[n][c][h*64+k] = sum_v Wr[c][h*64+v] * ctx[n][h][k][v]  (bf16 out)
// ctx partial reduction + 1/rowsum fused here (ctxp is L2-resident).
// ---------------------------------------------------------------------------
__global__ void __launch_bounds__(256) k_M(const float* __restrict__ Wr)
{
    int ct = blockIdx.x, h = blockIdx.y, n = blockIdx.z;
    __shared__ float Ws[64][65];
    __shared__ float Cs[64][65];
    int t = threadIdx.x;
    int nh = n * 8 + h;

    for (int e = t; e < 4096; e += 256) {
        int r = e >> 6, c = e & 63;
        Ws[r][c] = Wr[(size_t)(ct * 64 + r) * 512 + h * 64 + c];
        float sum = 0.f;
#pragma unroll
        for (int ch = 0; ch < 8; ++ch)
            sum += g_ctxp[(size_t)(nh * 8 + ch) * 4096 + e];
        Cs[r][c] = sum / g_rows[nh * 64 + r];
    }
    __syncthreads();

    int c0 = (t >> 4) << 2;
    int k0 = (t & 15) << 2;
    float acc[4][4] = {};
    for (int v = 0; v < 64; ++v) {
        float a_[4], b_[4];
#pragma unroll
        for (int i = 0; i < 4; ++i) a_[i] = Ws[c0 + i][v];
#pragma unroll
        for (int j = 0; j < 4; ++j) b_[j] = Cs[k0 + j][v];
#pragma unroll
        for (int i = 0; i < 4; ++i)
#pragma unroll
            for (int j = 0; j < 4; ++j)
                acc[i][j] = fmaf(a_[i], b_[j], acc[i][j]);
    }
#pragma unroll
    for (int i = 0; i < 4; ++i)
#pragma unroll
        for (int j = 0; j < 4; ++j)
            g_Mb[(size_t)n * 262144 + (size_t)(ct * 64 + c0 + i) * 512 + h * 64 + k0 + j]
                = __float2bfloat16(acc[i][j]);
}

// ---------------------------------------------------------------------------
extern "C" void kernel_launch(void* const* d_in, const int* in_sizes, int n_in,
                              void* d_out, int out_size)
{
    const float* x  = (const float*)d_in[0];
    const float* Wk = (const float*)d_in[1];
    const float* bk = (const float*)d_in[2];
    const float* Wq = (const float*)d_in[3];
    const float* bq = (const float*)d_in[4];
    const float* Wv = (const float*)d_in[5];
    const float* bv = (const float*)d_in[6];
    const float* Wr = (const float*)d_in[7];
    const float* br = (const float*)d_in[8];
    float* out = (float*)d_out;

    bf16* wb;
    cudaGetSymbolAddress((void**)&wb, g_wb);

    cudaFuncSetAttribute(k_proj, cudaFuncAttributeMaxDynamicSharedMemorySize, SMEMSZ);
    cudaFuncSetAttribute(k_out,  cudaFuncAttributeMaxDynamicSharedMemorySize, SMEMSZ);

    k_convw_all<<<768, 256>>>(Wk, Wq, Wv, wb);
    k_convx<<<dim3(128, 8, 8), 256>>>(x);
    k_proj<<<dim3(64, 6, 8), 512, SMEMSZ>>>(bk, bq, bv);
    k_ctx<<<dim3(64, 8), 256>>>();
    k_M<<<dim3(8, 8, 8), 256>>>(Wr);
    k_out<<<dim3(64, 2, 8), 512, SMEMSZ>>>(x, br, out);
}

// round 17
// speedup vs baseline: 1.1456x; 1.0179x over previous
#include <cuda_runtime.h>
#include <cuda_bf16.h>
#include <cstdint>
#include <cstddef>

#define NB 8
#define CC 512
#define WW 8192
#define HH 8

typedef __nv_bfloat16 bf16;

// ---------------- scratch (device globals; allocation-free) ----------------
__device__ bf16  g_xt  [(size_t)NB * WW * CC];   // x transposed [n][w][c] bf16
__device__ bf16  g_wb  [3 * CC * CC];            // Wk,Wq,Wv bf16
__device__ bf16  g_keysb[(size_t)NB * CC * WW];  // keys [n][c][w] bf16
__device__ bf16  g_valsb[(size_t)NB * CC * WW];  // values
__device__ bf16  g_sqt [(size_t)NB * WW * CC];   // softmax(Q) transposed [n][w][c]
__device__ bf16  g_Mb  [(size_t)NB * CC * CC];   // folded Wr@ctx^T (bf16)
__device__ float g_rows[NB * CC];                // sum(exp(keys)) per row
__device__ float g_ctxp[64 * 8 * 64 * 64];       // ctx partials

// ---------------- helpers (arch-neutral: ldmatrix / mma.sync / cp.async) ----
__device__ __forceinline__ uint32_t smem_u32(const void* p) {
    uint32_t a;
    asm("{ .reg .u64 t; cvta.to.shared.u64 t, %1; cvt.u32.u64 %0, t; }"
        : "=r"(a) : "l"(p));
    return a;
}
__device__ __forceinline__ void ldmx4(uint32_t* r, uint32_t addr) {
    asm volatile("ldmatrix.sync.aligned.m8n8.x4.shared.b16 {%0,%1,%2,%3}, [%4];"
                 : "=r"(r[0]), "=r"(r[1]), "=r"(r[2]), "=r"(r[3]) : "r"(addr));
}
__device__ __forceinline__ void mma_bf16(float* c, const uint32_t* a,
                                         const uint32_t b0, const uint32_t b1) {
    asm volatile(
        "mma.sync.aligned.m16n8k16.row.col.f32.bf16.bf16.f32 "
        "{%0,%1,%2,%3}, {%4,%5,%6,%7}, {%8,%9}, {%0,%1,%2,%3};"
        : "+f"(c[0]), "+f"(c[1]), "+f"(c[2]), "+f"(c[3])
        : "r"(a[0]), "r"(a[1]), "r"(a[2]), "r"(a[3]), "r"(b0), "r"(b1));
}
__device__ __forceinline__ void cp16(uint32_t dst, const void* src) {
    asm volatile("cp.async.cg.shared.global [%0], [%1], 16;" :: "r"(dst), "l"(src));
}
__device__ __forceinline__ void cp_commit() {
    asm volatile("cp.async.commit_group;");
}
template <int N>
__device__ __forceinline__ void cp_wait() {
    asm volatile("cp.async.wait_group %0;" :: "n"(N));
}

// ---------------------------------------------------------------------------
// HMMA GEMM body: D[256 x 128] = A[256 x 512] * B[colbase..+128, 512]^T
// bf16 K-major row-major operands. 512 threads, 16 warps (warp tile 64x32),
// 5-stage cp.async pipeline, BK=32; next-stage issue interleaved mid-chunk.
// mode: 0 = fp32 out + residual; 1 = bf16 out (smem-staged coalesced stores);
//       2 = bf16 + per-head column softmax + transposed write to g_sqt
// ---------------------------------------------------------------------------
#define BK 32
#define STRD 40                      // smem row stride (80 B; ldmatrix conflict-free)
#define NSTAGE 5
#define A_ELEMS (256 * STRD)
#define B_ELEMS (128 * STRD)
#define SMEMSZ (NSTAGE * (A_ELEMS + B_ELEMS) * 2)   // 153600 B
#define TSTR 264                     // transposed Q tile row stride (elements)
#define OSTR 136                     // mode-1 staging row stride (elements)

__device__ __forceinline__ void mm_issue(
    const bf16* __restrict__ A, const bf16* __restrict__ B,
    bf16* As, bf16* Bs, int stage, int k0, int colbase, int tid)
{
    uint32_t sa = smem_u32(As + (size_t)stage * A_ELEMS);
    uint32_t sb = smem_u32(Bs + (size_t)stage * B_ELEMS);
#pragma unroll
    for (int p = 0; p < 2; ++p) {
        int idx = tid + p * 512;
        int row = idx >> 2;                  // 0..255
        int seg = (idx & 3) << 3;            // 0,8,16,24
        cp16(sa + (uint32_t)(row * STRD + seg) * 2,
             A + (size_t)row * 512 + k0 + seg);
    }
    int rb = tid >> 2;                       // 0..127
    int segb = (tid & 3) << 3;
    cp16(sb + (uint32_t)(rb * STRD + segb) * 2,
         B + (size_t)(colbase + rb) * 512 + k0 + segb);
}

__device__ __forceinline__ void mm_body(
    const bf16* __restrict__ A,          // pre-offset to its 256-row slab
    const bf16* __restrict__ B,          // [8192 x 512] per-batch slab
    const float* __restrict__ bias,      // pre-offset [256]
    const float* __restrict__ resid,     // pre-offset rows (or nullptr)
    void* __restrict__ outp,             // pre-offset (mode2: g_sqt + n slab + mbrow)
    int mode)
{
    extern __shared__ bf16 dsm[];
    bf16* As = dsm;
    bf16* Bs = dsm + (size_t)NSTAGE * A_ELEMS;

    const int tid = threadIdx.x;
    const int lane = tid & 31;
    const int wid = tid >> 5;                // 0..15
    const int wm = (wid & 3) * 64;           // warp M base (0..192)
    const int wn = (wid >> 2) * 32;          // warp N base (0..96)
    const int colbase = blockIdx.x * 128;

    // hoisted per-warp ldmatrix offsets (element units, within a stage)
    const uint32_t aoff0 =
        (uint32_t)((wm + (lane & 15)) * STRD + ((lane >> 4) << 3));
    const uint32_t boffE[2] = {
        (uint32_t)((wn + (lane & 7) + ((lane >> 4) << 3)) * STRD
                   + (((lane >> 3) & 1) << 3)),
        (uint32_t)((wn + 16 + (lane & 7) + ((lane >> 4) << 3)) * STRD
                   + (((lane >> 3) & 1) << 3)) };

    float acc[4][4][4] = {};

    // prologue: stages 0..3
#pragma unroll
    for (int s = 0; s < 4; ++s) {
        mm_issue(A, B, As, Bs, s, s * BK, colbase, tid);
        cp_commit();
    }

    for (int ch = 0; ch < 16; ++ch) {
        cp_wait<3>();
        __syncthreads();
        const int cur = ch % NSTAGE;
        const uint32_t sa = smem_u32(As + (size_t)cur * A_ELEMS);
        const uint32_t sb = smem_u32(Bs + (size_t)cur * B_ELEMS);

        // ---- ks = 0 half-chunk ----
        {
            uint32_t a[4][4], b[2][4];
#pragma unroll
            for (int i = 0; i < 4; ++i)
                ldmx4(a[i], sa + (aoff0 + (uint32_t)(i * 16) * STRD) * 2);
#pragma unroll
            for (int j2 = 0; j2 < 2; ++j2)
                ldmx4(b[j2], sb + boffE[j2] * 2);
#pragma unroll
            for (int i = 0; i < 4; ++i)
#pragma unroll
                for (int j = 0; j < 4; ++j)
                    mma_bf16(acc[i][j], a[i], b[j >> 1][(j & 1) * 2],
                             b[j >> 1][(j & 1) * 2 + 1]);
        }

        // ---- interleaved next-stage issue (overlaps with tensor work) ----
        if (ch + 4 < 16)
            mm_issue(A, B, As, Bs, (ch + 4) % NSTAGE, (ch + 4) * BK,
                     colbase, tid);
        cp_commit();  // exactly one commit per iteration (group accounting)

        // ---- ks = 1 half-chunk ----
        {
            uint32_t a[4][4], b[2][4];
            const uint32_t kk = 32u;         // 16 elems * 2 B
#pragma unroll
            for (int i = 0; i < 4; ++i)
                ldmx4(a[i], sa + (aoff0 + (uint32_t)(i * 16) * STRD) * 2 + kk);
#pragma unroll
            for (int j2 = 0; j2 < 2; ++j2)
                ldmx4(b[j2], sb + boffE[j2] * 2 + kk);
#pragma unroll
            for (int i = 0; i < 4; ++i)
#pragma unroll
                for (int j = 0; j < 4; ++j)
                    mma_bf16(acc[i][j], a[i], b[j >> 1][(j & 1) * 2],
                             b[j >> 1][(j & 1) * 2 + 1]);
        }
    }

    const int mrow = wm + (lane >> 2);
    const int ncol = wn + 2 * (lane & 3);

    if (mode == 2) {
        // bias in place
#pragma unroll
        for (int i = 0; i < 4; ++i) {
            float b0 = bias[mrow + i * 16], b1 = bias[mrow + i * 16 + 8];
#pragma unroll
            for (int j = 0; j < 4; ++j) {
                acc[i][j][0] += b0; acc[i][j][1] += b0;
                acc[i][j][2] += b1; acc[i][j][3] += b1;
            }
        }
        // per-column softmax over this warp's 64 rows (exactly one head)
#pragma unroll
        for (int j = 0; j < 4; ++j)
#pragma unroll
            for (int q = 0; q < 2; ++q) {
                float mx = -1e30f;
#pragma unroll
                for (int i = 0; i < 4; ++i)
                    mx = fmaxf(mx, fmaxf(acc[i][j][q], acc[i][j][q + 2]));
                mx = fmaxf(mx, __shfl_xor_sync(0xffffffffu, mx, 4));
                mx = fmaxf(mx, __shfl_xor_sync(0xffffffffu, mx, 8));
                mx = fmaxf(mx, __shfl_xor_sync(0xffffffffu, mx, 16));
                float s = 0.f;
#pragma unroll
                for (int i = 0; i < 4; ++i) {
                    acc[i][j][q]     = __expf(acc[i][j][q] - mx);
                    acc[i][j][q + 2] = __expf(acc[i][j][q + 2] - mx);
                    s += acc[i][j][q] + acc[i][j][q + 2];
                }
                s += __shfl_xor_sync(0xffffffffu, s, 4);
                s += __shfl_xor_sync(0xffffffffu, s, 8);
                s += __shfl_xor_sync(0xffffffffu, s, 16);
                float inv = 1.f / s;
#pragma unroll
                for (int i = 0; i < 4; ++i) {
                    acc[i][j][q] *= inv; acc[i][j][q + 2] *= inv;
                }
            }
        // transpose through smem (pipeline buffers are dead now)
        __syncthreads();
        bf16* tile = dsm;                    // [128 w][TSTR] channels
#pragma unroll
        for (int i = 0; i < 4; ++i) {
            int m0 = mrow + i * 16;
#pragma unroll
            for (int j = 0; j < 4; ++j) {
                int nb = ncol + j * 8;
                float* c = acc[i][j];
                tile[(size_t)nb * TSTR + m0]           = __float2bfloat16(c[0]);
                tile[(size_t)(nb + 1) * TSTR + m0]     = __float2bfloat16(c[1]);
                tile[(size_t)nb * TSTR + m0 + 8]       = __float2bfloat16(c[2]);
                tile[(size_t)(nb + 1) * TSTR + m0 + 8] = __float2bfloat16(c[3]);
            }
        }
        __syncthreads();
        // coalesced store: g_sqt[(colbase+w)*CC + mbrow + c]
        bf16* oq = (bf16*)outp;
#pragma unroll
        for (int p = 0; p < 8; ++p) {
            int idx = tid + p * 512;
            int nl = idx >> 5;               // 0..127
            int seg = (idx & 31) * 8;        // 0..248
            *(uint4*)(oq + (size_t)(colbase + nl) * CC + seg) =
                *(uint4*)&tile[(size_t)nl * TSTR + seg];
        }
        return;
    }

    if (mode == 1) {
        // stage bf16 tile in (dead) pipeline smem for full-sector stores
        __syncthreads();
        bf16* tile = dsm;                    // [256 m][OSTR cols]
#pragma unroll
        for (int i = 0; i < 4; ++i) {
            int m0 = mrow + i * 16;
            float b0 = bias[m0];
            float b1 = bias[m0 + 8];
#pragma unroll
            for (int j = 0; j < 4; ++j) {
                int nb = ncol + j * 8;       // local col 0..127
                float* c = acc[i][j];
                *(__nv_bfloat162*)&tile[(size_t)m0 * OSTR + nb] =
                    __floats2bfloat162_rn(c[0] + b0, c[1] + b0);
                *(__nv_bfloat162*)&tile[(size_t)(m0 + 8) * OSTR + nb] =
                    __floats2bfloat162_rn(c[2] + b1, c[3] + b1);
            }
        }
        __syncthreads();
        bf16* o = (bf16*)outp;
#pragma unroll
        for (int p = 0; p < 8; ++p) {
            int idx = tid + p * 512;
            int row = idx >> 4;              // 0..255
            int seg = (idx & 15) * 8;        // 0..120
            *(uint4*)(o + (size_t)row * WW + colbase + seg) =
                *(uint4*)&tile[(size_t)row * OSTR + seg];
        }
        return;
    }

    // mode 0: fp32 + residual; batch ALL resid loads first (MLP), then FFMA+STG
    const int ncolg = colbase + ncol;
    float2 rres[4][4][2];
#pragma unroll
    for (int i = 0; i < 4; ++i) {
        int m0 = mrow + i * 16;
#pragma unroll
        for (int j = 0; j < 4; ++j) {
            int n = ncolg + j * 8;
            rres[i][j][0] = *(const float2*)(resid + (size_t)m0 * WW + n);
            rres[i][j][1] = *(const float2*)(resid + (size_t)(m0 + 8) * WW + n);
        }
    }
#pragma unroll
    for (int i = 0; i < 4; ++i) {
        int m0 = mrow + i * 16;
        float b0 = bias[m0];
        float b1 = bias[m0 + 8];
#pragma unroll
        for (int j = 0; j < 4; ++j) {
            int n = ncolg + j * 8;
            float* c = acc[i][j];
            float* o = (float*)outp;
            float2 o0 = { c[0] + b0 + rres[i][j][0].x, c[1] + b0 + rres[i][j][0].y };
            float2 o1 = { c[2] + b1 + rres[i][j][1].x, c[3] + b1 + rres[i][j][1].y };
            *(float2*)(o + (size_t)m0 * WW + n) = o0;
            *(float2*)(o + (size_t)(m0 + 8) * WW + n) = o1;
        }
    }
}

// ---------------------------------------------------------------------------
// single conversion kernel: all 3 weights + zero g_rows
// ---------------------------------------------------------------------------
__global__ void __launch_bounds__(256)
k_convw_all(const float* __restrict__ Wk, const float* __restrict__ Wq,
            const float* __restrict__ Wv, bf16* __restrict__ d)
{
    int gid = blockIdx.x * 256 + threadIdx.x;          // 0..196607
    if (gid < NB * CC) g_rows[gid] = 0.f;
    int sect = gid >> 16;
    int local = gid & 65535;
    const float* s = (sect == 0 ? Wk : sect == 1 ? Wq : Wv);
    int i = local * 4;
    float4 v = *(const float4*)(s + i);
    __nv_bfloat162 o[2];
    o[0] = __floats2bfloat162_rn(v.x, v.y);
    o[1] = __floats2bfloat162_rn(v.z, v.w);
    *(uint2*)(d + (size_t)sect * 262144 + i) = *(uint2*)o;
}

// 64x64 transpose tiles: 128B-coalesced reads and (bf16x2-packed) writes
__global__ void __launch_bounds__(256)
k_convx(const float* __restrict__ x)
{
    __shared__ float tile[64][65];
    int n = blockIdx.z, c0 = blockIdx.y * 64, w0 = blockIdx.x * 64;
    int t = threadIdx.x;
    int tx = t & 63, ty = t >> 6;
    const float* xb = x + (size_t)n * CC * WW;
#pragma unroll
    for (int i = ty; i < 64; i += 4)
        tile[i][tx] = xb[(size_t)(c0 + i) * WW + w0 + tx];
    __syncthreads();
    bf16* ob = g_xt + (size_t)n * WW * CC;
    int cpair = (t & 31) * 2, wr = t >> 5;
#pragma unroll
    for (int i = wr; i < 64; i += 8) {
        __nv_bfloat162 v = __floats2bfloat162_rn(tile[cpair][i], tile[cpair + 1][i]);
        *(__nv_bfloat162*)(ob + (size_t)(w0 + i) * CC + c0 + cpair) = v;
    }
}

// ---------------------------------------------------------------------------
// GEMM wrappers
// ---------------------------------------------------------------------------
__global__ void __launch_bounds__(512, 1)
k_proj(const float* __restrict__ bk, const float* __restrict__ bq,
       const float* __restrict__ bv)
{
    int mtile = blockIdx.y;                  // 0..5
    int sect = mtile >> 1;                   // 0=K 1=Q 2=V
    int mbrow = (mtile & 1) * 256;
    int n = blockIdx.z;
    const bf16* A = g_wb + (size_t)sect * CC * CC + (size_t)mbrow * CC;
    const bf16* B = g_xt + (size_t)n * WW * CC;
    const float* bias = (sect == 0 ? bk : sect == 1 ? bq : bv) + mbrow;
    if (sect == 1) {
        bf16* out = g_sqt + (size_t)n * WW * CC + mbrow;   // channel offset
        mm_body(A, B, bias, nullptr, out, 2);
    } else {
        bf16* out = (sect == 0 ? g_keysb : g_valsb)
                    + (size_t)n * CC * WW + (size_t)mbrow * WW;
        mm_body(A, B, bias, nullptr, out, 1);
    }
}

__global__ void __launch_bounds__(512, 1)
k_out(const float* __restrict__ x, const float* __restrict__ br,
      float* __restrict__ out)
{
    int mbrow = blockIdx.y * 256;
    int n = blockIdx.z;
    const bf16* A = g_Mb + (size_t)n * CC * CC + (size_t)mbrow * CC;
    const bf16* B = g_sqt + (size_t)n * WW * CC;
    const float* resid = x + (size_t)n * CC * WW + (size_t)mbrow * WW;
    float* O = out + (size_t)n * CC * WW + (size_t)mbrow * WW;
    mm_body(A, B, br + mbrow, resid, O, 0);
}

// ---------------------------------------------------------------------------
// ctx partials via HMMA: exp(K) @ V^T over 1024-wide w chunks, fused row sums.
// grid (64 nh, 8 chunks), 256 threads. smem [64][72] bf16, double-buffered.
// ---------------------------------------------------------------------------
#define CSTRD 72

__global__ void __launch_bounds__(256) k_ctx()
{
    __shared__ bf16 Ks[2][64 * CSTRD];
    __shared__ bf16 Vs[2][64 * CSTRD];

    int nh = blockIdx.x, chunk = blockIdx.y, t = threadIdx.x;
    int lane = t & 31, wid = t >> 5;
    int rowbase = nh * 64;
    int wbase = chunk * 1024;
    int lr = t >> 2;
    int seg = (t & 3) * 16;
    const bf16* kg = g_keysb + (size_t)(rowbase + lr) * WW + wbase + seg;
    const bf16* vg = g_valsb + (size_t)(rowbase + lr) * WW + wbase + seg;

    int wm = (wid & 3) * 16;
    int wn = (wid >> 2) * 32;

    float acc[4][4] = {};
    float srow = 0.f;

    uint4 kr[2], vr[2];
    kr[0] = *(const uint4*)kg;       kr[1] = *(const uint4*)(kg + 8);
    vr[0] = *(const uint4*)vg;       vr[1] = *(const uint4*)(vg + 8);

    for (int s = 0; s < 16; ++s) {
        const int b = s & 1;
        uint4 ke[2];
#pragma unroll
        for (int u = 0; u < 2; ++u) {
            const __nv_bfloat162* kh = (const __nv_bfloat162*)&kr[u];
            __nv_bfloat162* eo = (__nv_bfloat162*)&ke[u];
#pragma unroll
            for (int i = 0; i < 4; ++i) {
                float2 f = __bfloat1622float2(kh[i]);
                float e0 = __expf(f.x), e1 = __expf(f.y);
                srow += e0 + e1;
                eo[i] = __floats2bfloat162_rn(e0, e1);
            }
        }
        bf16* kst = &Ks[b][lr * CSTRD + seg];
        bf16* vst = &Vs[b][lr * CSTRD + seg];
        *(uint4*)kst = ke[0];        *(uint4*)(kst + 8) = ke[1];
        *(uint4*)vst = vr[0];        *(uint4*)(vst + 8) = vr[1];
        __syncthreads();
        if (s < 15) {
            const bf16* kg2 = kg + (s + 1) * 64;
            const bf16* vg2 = vg + (s + 1) * 64;
            kr[0] = *(const uint4*)kg2; kr[1] = *(const uint4*)(kg2 + 8);
            vr[0] = *(const uint4*)vg2; vr[1] = *(const uint4*)(vg2 + 8);
        }
        const uint32_t sk = smem_u32(&Ks[b][0]);
        const uint32_t sv = smem_u32(&Vs[b][0]);
#pragma unroll
        for (int ks = 0; ks < 4; ++ks) {
            uint32_t a[4], bb[2][4];
            const int kA = ks * 16 + ((lane >> 4) << 3);
            const int kB = ks * 16 + (((lane >> 3) & 1) << 3);
            ldmx4(a, sk + (uint32_t)((wm + (lane & 15)) * CSTRD + kA) * 2);
#pragma unroll
            for (int j2 = 0; j2 < 2; ++j2)
                ldmx4(bb[j2], sv +
                      (uint32_t)((wn + j2 * 16 + (lane & 7) + ((lane >> 4) << 3))
                                 * CSTRD + kB) * 2);
#pragma unroll
            for (int j = 0; j < 4; ++j)
                mma_bf16(acc[j], a, bb[j >> 1][(j & 1) * 2],
                         bb[j >> 1][(j & 1) * 2 + 1]);
        }
    }

    srow += __shfl_xor_sync(0xffffffffu, srow, 1);
    srow += __shfl_xor_sync(0xffffffffu, srow, 2);
    if ((t & 3) == 0) atomicAdd(&g_rows[rowbase + lr], srow);

    float* op = g_ctxp + (size_t)(nh * 8 + chunk) * 4096;
    int r0 = wm + (lane >> 2);
    int c0 = wn + (lane & 3) * 2;
#pragma unroll
    for (int j = 0; j < 4; ++j) {
        int c = c0 + j * 8;
        op[r0 * 64 + c]           = acc[j][0];
        op[r0 * 64 + c + 1]       = acc[j][1];
        op[(r0 + 8) * 64 + c]     = acc[j][2];
        op[(r0 + 8) * 64 + c + 1] = acc[j][3];
    }
}

// ---------------------------------------------------------------------------
// M[n][c][h*64+k] = sum_v Wr[c][h*64+v] * ctx[n][h][k][v]  (bf16 out)
// ctx partial reduction + 1/rowsum fused here (ctxp is L2-resident).
// ---------------------------------------------------------------------------
__global__ void __launch_bounds__(256) k_M(const float* __restrict__ Wr)
{
    int ct = blockIdx.x, h = blockIdx.y, n = blockIdx.z;
    __shared__ float Ws[64][65];
    __shared__ float Cs[64][65];
    int t = threadIdx.x;
    int nh = n * 8 + h;

    for (int e = t; e < 4096; e += 256) {
        int r = e >> 6, c = e & 63;
        Ws[r][c] = Wr[(size_t)(ct * 64 + r) * 512 + h * 64 + c];
        float sum = 0.f;
#pragma unroll
        for (int ch = 0; ch < 8; ++ch)
            sum += g_ctxp[(size_t)(nh * 8 + ch) * 4096 + e];
        Cs[r][c] = sum / g_rows[nh * 64 + r];
    }
    __syncthreads();

    int c0 = (t >> 4) << 2;
    int k0 = (t & 15) << 2;
    float acc[4][4] = {};
    for (int v = 0; v < 64; ++v) {
        float a_[4], b_[4];
#pragma unroll
        for (int i = 0; i < 4; ++i) a_[i] = Ws[c0 + i][v];
#pragma unroll
        for (int j = 0; j < 4; ++j) b_[j] = Cs[k0 + j][v];
#pragma unroll
        for (int i = 0; i < 4; ++i)
#pragma unroll
            for (int j = 0; j < 4; ++j)
                acc[i][j] = fmaf(a_[i], b_[j], acc[i][j]);
    }
#pragma unroll
    for (int i = 0; i < 4; ++i)
#pragma unroll
        for (int j = 0; j < 4; ++j)
            g_Mb[(size_t)n * 262144 + (size_t)(ct * 64 + c0 + i) * 512 + h * 64 + k0 + j]
                = __float2bfloat16(acc[i][j]);
}

// ---------------------------------------------------------------------------
extern "C" void kernel_launch(void* const* d_in, const int* in_sizes, int n_in,
                              void* d_out, int out_size)
{
    const float* x  = (const float*)d_in[0];
    const float* Wk = (const float*)d_in[1];
    const float* bk = (const float*)d_in[2];
    const float* Wq = (const float*)d_in[3];
    const float* bq = (const float*)d_in[4];
    const float* Wv = (const float*)d_in[5];
    const float* bv = (const float*)d_in[6];
    const float* Wr = (const float*)d_in[7];
    const float* br = (const float*)d_in[8];
    float* out = (float*)d_out;

    bf16* wb;
    cudaGetSymbolAddress((void**)&wb, g_wb);

    cudaFuncSetAttribute(k_proj, cudaFuncAttributeMaxDynamicSharedMemorySize, SMEMSZ);
    cudaFuncSetAttribute(k_out,  cudaFuncAttributeMaxDynamicSharedMemorySize, SMEMSZ);

    k_convw_all<<<768, 256>>>(Wk, Wq, Wv, wb);
    k_convx<<<dim3(128, 8, 8), 256>>>(x);
    k_proj<<<dim3(64, 6, 8), 512, SMEMSZ>>>(bk, bq, bv);
    k_ctx<<<dim3(64, 8), 256>>>();
    k_M<<<dim3(8, 8, 8), 256>>>(Wr);
    k_out<<<dim3(64, 2, 8), 512, SMEMSZ>>>(x, br, out);
}